// round 1
// baseline (speedup 1.0000x reference)
#include <cuda_runtime.h>
#include <math.h>

#define BATCH 4
#define SEQ   2048
#define DM    1024
#define NH    16
#define HD    64
#define QKVN  (3*DM)

// Scratch buffers (no dynamic allocation allowed)
__device__ float g_qkv[(size_t)BATCH * SEQ * QKVN];   // [B,S,3D]
__device__ float g_attn[(size_t)BATCH * SEQ * DM];    // [B,S,D]

// ---------------------------------------------------------------------------
// Register-blocked SGEMM: C[M,N] = A[M,K] @ B[K,N], all row-major fp32.
// BM=BN=128, BK=8, 256 threads, 8x8 micro-tile per thread.
// M % 128 == 0, N % 128 == 0, K % 8 == 0 (true for all our shapes).
// ---------------------------------------------------------------------------
__global__ __launch_bounds__(256)
void sgemm128(const float* __restrict__ A, const float* __restrict__ B,
              float* __restrict__ C, int M, int N, int K)
{
    __shared__ float As[8][128];   // transposed A tile: As[k][m]
    __shared__ float Bs[8][128];   // Bs[k][n]

    const int tid = threadIdx.x;
    const int brow = blockIdx.y * 128;
    const int bcol = blockIdx.x * 128;

    const int ty = tid >> 4;       // 0..15  -> row group
    const int tx = tid & 15;       // 0..15  -> col group

    const int a_r = tid >> 1;          // 0..127
    const int a_c = (tid & 1) * 4;     // 0 or 4
    const int b_r = tid >> 5;          // 0..7
    const int b_c = (tid & 31) * 4;    // 0..124

    float acc[8][8];
#pragma unroll
    for (int i = 0; i < 8; i++)
#pragma unroll
        for (int j = 0; j < 8; j++) acc[i][j] = 0.f;

    const float* Ap = A + (size_t)(brow + a_r) * K + a_c;
    const float* Bp = B + (size_t)b_r * N + bcol + b_c;

    for (int k0 = 0; k0 < K; k0 += 8) {
        float4 av = *(const float4*)(Ap + k0);
        As[a_c + 0][a_r] = av.x;
        As[a_c + 1][a_r] = av.y;
        As[a_c + 2][a_r] = av.z;
        As[a_c + 3][a_r] = av.w;
        float4 bv = *(const float4*)(Bp + (size_t)k0 * N);
        *(float4*)&Bs[b_r][b_c] = bv;
        __syncthreads();

#pragma unroll
        for (int k = 0; k < 8; k++) {
            float a[8], b[8];
#pragma unroll
            for (int i = 0; i < 8; i++) a[i] = As[k][ty * 8 + i];
#pragma unroll
            for (int j = 0; j < 8; j++) b[j] = Bs[k][tx * 8 + j];
#pragma unroll
            for (int i = 0; i < 8; i++)
#pragma unroll
                for (int j = 0; j < 8; j++)
                    acc[i][j] += a[i] * b[j];
        }
        __syncthreads();
    }

#pragma unroll
    for (int i = 0; i < 8; i++) {
        float* Cp = C + (size_t)(brow + ty * 8 + i) * N + bcol + tx * 8;
        *(float4*)(Cp + 0) = make_float4(acc[i][0], acc[i][1], acc[i][2], acc[i][3]);
        *(float4*)(Cp + 4) = make_float4(acc[i][4], acc[i][5], acc[i][6], acc[i][7]);
    }
}

// ---------------------------------------------------------------------------
// Flash-attention: one block per (q-tile of 64, head, batch). 64 threads,
// each thread owns one query row. Q in registers, K/V staged via smem.
// ---------------------------------------------------------------------------
#define ATTN_SMEM_FLOATS (2 * 64 * 65 + 64 * 65 + 64 * 64)
#define ATTN_SMEM_BYTES  (ATTN_SMEM_FLOATS * 4)

__global__ __launch_bounds__(64)
void attn_kernel()
{
    extern __shared__ float sm[];
    float* qs = sm;                 // [64][65]
    float* ks = qs + 64 * 65;       // [64][65]
    float* ss = ks + 64 * 65;       // [64][65]
    float* vs = ss + 64 * 65;       // [64][64]

    const int b  = blockIdx.z;
    const int h  = blockIdx.y;
    const int q0 = blockIdx.x * 64;
    const int r  = threadIdx.x;     // 0..63, this thread's query row

    const float scale = 0.125f;     // 1/sqrt(64)

    // Stage Q tile (coalesced), then copy own row to registers.
    for (int i = 0; i < 64; i++)
        qs[i * 65 + r] = g_qkv[((size_t)(b * SEQ + q0 + i)) * QKVN + h * HD + r];
    __syncthreads();

    float qreg[64];
#pragma unroll
    for (int d = 0; d < 64; d++) qreg[d] = qs[r * 65 + d];

    float acc[64];
#pragma unroll
    for (int d = 0; d < 64; d++) acc[d] = 0.f;
    float mval = -1e30f;
    float lval = 0.f;

    for (int kt = 0; kt < SEQ; kt += 64) {
        __syncthreads();
        for (int i = 0; i < 64; i++) {
            size_t base = ((size_t)(b * SEQ + kt + i)) * QKVN;
            ks[i * 65 + r] = g_qkv[base + DM     + h * HD + r];
            vs[i * 64 + r] = g_qkv[base + 2 * DM + h * HD + r];
        }
        __syncthreads();

        // S = scale * Q K^T for this row; track running max
        float rmax = mval;
        for (int j = 0; j < 64; j++) {
            float s0 = 0.f, s1 = 0.f, s2 = 0.f, s3 = 0.f;
#pragma unroll
            for (int d = 0; d < 64; d += 4) {
                s0 += qreg[d + 0] * ks[j * 65 + d + 0];
                s1 += qreg[d + 1] * ks[j * 65 + d + 1];
                s2 += qreg[d + 2] * ks[j * 65 + d + 2];
                s3 += qreg[d + 3] * ks[j * 65 + d + 3];
            }
            float s = ((s0 + s1) + (s2 + s3)) * scale;
            ss[r * 65 + j] = s;
            rmax = fmaxf(rmax, s);
        }

        const float corr = __expf(mval - rmax);
        mval = rmax;

        float lsum = 0.f;
        for (int j = 0; j < 64; j++) {
            float p = __expf(ss[r * 65 + j] - mval);
            ss[r * 65 + j] = p;
            lsum += p;
        }
        lval = lval * corr + lsum;

#pragma unroll
        for (int d = 0; d < 64; d++) acc[d] *= corr;

        for (int j = 0; j < 64; j++) {
            const float p = ss[r * 65 + j];
#pragma unroll
            for (int d = 0; d < 64; d++)
                acc[d] += p * vs[j * 64 + d];
        }
    }

    const float inv = 1.f / lval;
    float* outp = g_attn + ((size_t)(b * SEQ + q0 + r)) * DM + h * HD;
#pragma unroll
    for (int d = 0; d < 64; d++) outp[d] = acc[d] * inv;
}

// ---------------------------------------------------------------------------
extern "C" void kernel_launch(void* const* d_in, const int* in_sizes, int n_in,
                              void* d_out, int out_size)
{
    const float* x     = (const float*)d_in[0];   // [4,2048,1024]
    const float* w_qkv = (const float*)d_in[1];   // [1024,3072]
    const float* w_out = (const float*)d_in[2];   // [1024,1024]
    float* out = (float*)d_out;                   // [4,2048,1024]

    float* qkv_ptr;
    float* attn_ptr;
    cudaGetSymbolAddress((void**)&qkv_ptr,  g_qkv);
    cudaGetSymbolAddress((void**)&attn_ptr, g_attn);

    cudaFuncSetAttribute(attn_kernel,
                         cudaFuncAttributeMaxDynamicSharedMemorySize,
                         ATTN_SMEM_BYTES);

    const int M = BATCH * SEQ;  // 8192

    // 1) QKV projection: [8192,1024] @ [1024,3072]
    {
        dim3 grid(QKVN / 128, M / 128);
        sgemm128<<<grid, 256>>>(x, w_qkv, qkv_ptr, M, QKVN, DM);
    }

    // 2) Attention
    {
        dim3 grid(SEQ / 64, NH, BATCH);
        attn_kernel<<<grid, 64, ATTN_SMEM_BYTES>>>();
    }

    // 3) Output projection: [8192,1024] @ [1024,1024]
    {
        dim3 grid(DM / 128, M / 128);
        sgemm128<<<grid, 256>>>(attn_ptr, w_out, out, M, DM, DM);
    }
}

// round 3
// speedup vs baseline: 1.2308x; 1.2308x over previous
#include <cuda_runtime.h>
#include <cuda_bf16.h>
#include <math.h>
#include <cstdint>

#define BATCH 4
#define SEQ   2048
#define DM    1024
#define NH    16
#define HD    64
#define QKVN  (3*DM)

// Scratch buffers (no dynamic allocation allowed)
__device__ float g_qkv[(size_t)BATCH * SEQ * QKVN];   // [B,S,3D]
__device__ float g_attn[(size_t)BATCH * SEQ * DM];    // [B,S,D]

// ===========================================================================
// Warp-level MMA helpers (base ISA: works on plain sm_103 target)
// ===========================================================================
__device__ __forceinline__ void ldsm_x4(uint32_t* r, uint32_t addr) {
    asm volatile("ldmatrix.sync.aligned.m8n8.x4.shared.b16 {%0,%1,%2,%3}, [%4];"
        : "=r"(r[0]), "=r"(r[1]), "=r"(r[2]), "=r"(r[3]) : "r"(addr));
}
__device__ __forceinline__ void ldsm_x4_t(uint32_t* r, uint32_t addr) {
    asm volatile("ldmatrix.sync.aligned.m8n8.x4.trans.shared.b16 {%0,%1,%2,%3}, [%4];"
        : "=r"(r[0]), "=r"(r[1]), "=r"(r[2]), "=r"(r[3]) : "r"(addr));
}
__device__ __forceinline__ void mma16816(float* d, const uint32_t* a, const uint32_t* b) {
    asm volatile(
        "mma.sync.aligned.m16n8k16.row.col.f32.bf16.bf16.f32 "
        "{%0,%1,%2,%3}, {%4,%5,%6,%7}, {%8,%9}, {%0,%1,%2,%3};"
        : "+f"(d[0]), "+f"(d[1]), "+f"(d[2]), "+f"(d[3])
        : "r"(a[0]), "r"(a[1]), "r"(a[2]), "r"(a[3]), "r"(b[0]), "r"(b[1]));
}

__device__ __forceinline__ uint32_t smem_to_u32(const void* smem_ptr) {
    uint32_t addr;
    asm("{ .reg .u64 tmp; cvta.to.shared.u64 tmp, %1; cvt.u32.u64 %0, tmp; }"
        : "=r"(addr) : "l"(smem_ptr));
    return addr;
}

__device__ __forceinline__ uint32_t pack_bf16_pair(float x0, float x1) {
    __nv_bfloat162 t = __floats2bfloat162_rn(x0, x1);
    return *(uint32_t*)&t;
}
__device__ __forceinline__ void split_f32(float x, float& h, float& l) {
    __nv_bfloat16 hb = __float2bfloat16_rn(x);
    h = __bfloat162float(hb);
    l = x - h;
}

// ===========================================================================
// HMMA bf16x3 GEMM: C[M,N] = A[M,K] @ B[K,N], fp32 in/out.
// CTA tile 128x128, BK=32, 256 threads (8 warps, 32x64 warp tiles).
// M,N multiples of 128; K multiple of 32.
// ===========================================================================
#define SA 40    // As row stride (bf16 elems), 80B = 16B-aligned
#define SB 136   // Bs row stride (bf16 elems), 272B = 16B-aligned
#define ABUF_B (128 * SA * 2)            // 10240 bytes (one of hi/lo)
#define BBUF_B (32 * SB * 2)             // 8704 bytes
#define BUF_B  (2 * ABUF_B + 2 * BBUF_B) // 37888 bytes per stage
#define GEMM_SMEM_BYTES (2 * BUF_B)      // 75776

__global__ __launch_bounds__(256, 1)
void gemm_hmma3(const float* __restrict__ A, const float* __restrict__ B,
                float* __restrict__ C, int M, int N, int K)
{
    extern __shared__ char smem[];
    const uint32_t smem_u32 = smem_to_u32(smem);

    const int tid = threadIdx.x;
    const int wid = tid >> 5;
    const int lid = tid & 31;
    const int brow = blockIdx.y * 128;
    const int bcol = blockIdx.x * 128;

    const int wr = wid >> 1;     // 0..3 -> m offset wr*32
    const int wc = wid & 1;      // 0..1 -> n offset wc*64

    float acc[2][8][4];
#pragma unroll
    for (int i = 0; i < 2; i++)
#pragma unroll
        for (int j = 0; j < 8; j++)
#pragma unroll
            for (int q = 0; q < 4; q++) acc[i][j][q] = 0.f;

    // Staging map: idx = tid*4 + j over 1024 float4 slots per tile
    // A tile 128x32 f32: row = idx>>3, col = (idx&7)*4
    // B tile 32x128 f32: row = idx>>5, col = (idx&31)*4
    float4 pa[4], pb[4];

    const int nkt = K >> 5;

    // ---- prefetch k-tile 0 ----
#pragma unroll
    for (int j = 0; j < 4; j++) {
        int idx = tid * 4 + j;
        pa[j] = *(const float4*)(A + (size_t)(brow + (idx >> 3)) * K + (idx & 7) * 4);
        pb[j] = *(const float4*)(B + (size_t)(idx >> 5) * N + bcol + (idx & 31) * 4);
    }

    // convert+store helper is inlined manually in the loop
    for (int kt = 0; kt < nkt; kt++) {
        const int sW = kt & 1;  // buffer being written this iteration holds tile kt
        {
            char* base = smem + sW * BUF_B;
#pragma unroll
            for (int j = 0; j < 4; j++) {
                int idx = tid * 4 + j;
                // A
                {
                    int r = idx >> 3, c = (idx & 7) * 4;
                    float h0,l0,h1,l1,h2,l2,h3,l3;
                    split_f32(pa[j].x, h0, l0); split_f32(pa[j].y, h1, l1);
                    split_f32(pa[j].z, h2, l2); split_f32(pa[j].w, h3, l3);
                    uint32_t off = (uint32_t)(r * SA + c) * 2;
                    *(uint2*)(base + off) =
                        make_uint2(pack_bf16_pair(h0, h1), pack_bf16_pair(h2, h3));
                    *(uint2*)(base + ABUF_B + off) =
                        make_uint2(pack_bf16_pair(l0, l1), pack_bf16_pair(l2, l3));
                }
                // B
                {
                    int r = idx >> 5, c = (idx & 31) * 4;
                    float h0,l0,h1,l1,h2,l2,h3,l3;
                    split_f32(pb[j].x, h0, l0); split_f32(pb[j].y, h1, l1);
                    split_f32(pb[j].z, h2, l2); split_f32(pb[j].w, h3, l3);
                    uint32_t off = (uint32_t)(r * SB + c) * 2;
                    *(uint2*)(base + 2 * ABUF_B + off) =
                        make_uint2(pack_bf16_pair(h0, h1), pack_bf16_pair(h2, h3));
                    *(uint2*)(base + 2 * ABUF_B + BBUF_B + off) =
                        make_uint2(pack_bf16_pair(l0, l1), pack_bf16_pair(l2, l3));
                }
            }
        }
        __syncthreads();

        // prefetch next k-tile while doing MMA on this one
        if (kt + 1 < nkt) {
            const int k0 = (kt + 1) << 5;
#pragma unroll
            for (int j = 0; j < 4; j++) {
                int idx = tid * 4 + j;
                pa[j] = *(const float4*)(A + (size_t)(brow + (idx >> 3)) * K + k0 + (idx & 7) * 4);
                pb[j] = *(const float4*)(B + (size_t)(k0 + (idx >> 5)) * N + bcol + (idx & 31) * 4);
            }
        }

        // ---- MMA over buffer sW: 2 k-steps of 16 ----
        const uint32_t aHi = smem_u32 + sW * BUF_B;
        const uint32_t aLo = aHi + ABUF_B;
        const uint32_t bHi = aHi + 2 * ABUF_B;
        const uint32_t bLo = bHi + BBUF_B;
#pragma unroll
        for (int ks = 0; ks < 2; ks++) {
            uint32_t ahi[2][4], alo[2][4];
#pragma unroll
            for (int mi = 0; mi < 2; mi++) {
                uint32_t row = wr * 32 + mi * 16 + (lid & 15);
                uint32_t col = ks * 16 + (lid >> 4) * 8;
                uint32_t off = (row * SA + col) * 2;
                ldsm_x4(ahi[mi], aHi + off);
                ldsm_x4(alo[mi], aLo + off);
            }
            uint32_t bhi[4][4], blo[4][4];
#pragma unroll
            for (int nb = 0; nb < 4; nb++) {
                uint32_t row = ks * 16 + (lid & 15);
                uint32_t col = wc * 64 + nb * 16 + (lid >> 4) * 8;
                uint32_t off = (row * SB + col) * 2;
                ldsm_x4_t(bhi[nb], bHi + off);
                ldsm_x4_t(blo[nb], bLo + off);
            }
#pragma unroll
            for (int mi = 0; mi < 2; mi++)
#pragma unroll
                for (int nb = 0; nb < 4; nb++) {
                    float* d0 = acc[mi][nb * 2];
                    float* d1 = acc[mi][nb * 2 + 1];
                    mma16816(d0, ahi[mi], &bhi[nb][0]);
                    mma16816(d1, ahi[mi], &bhi[nb][2]);
                    mma16816(d0, ahi[mi], &blo[nb][0]);
                    mma16816(d1, ahi[mi], &blo[nb][2]);
                    mma16816(d0, alo[mi], &bhi[nb][0]);
                    mma16816(d1, alo[mi], &bhi[nb][2]);
                }
        }
        __syncthreads();
    }

    // ---- epilogue ----
    const int qrow = lid >> 2;        // 0..7
    const int qcol = (lid & 3) * 2;   // 0,2,4,6
#pragma unroll
    for (int mi = 0; mi < 2; mi++) {
        int r0 = brow + wr * 32 + mi * 16 + qrow;
#pragma unroll
        for (int nb = 0; nb < 8; nb++) {
            int c0 = bcol + wc * 64 + nb * 8 + qcol;
            float* d = acc[mi][nb];
            *(float2*)(C + (size_t)r0 * N + c0)       = make_float2(d[0], d[1]);
            *(float2*)(C + (size_t)(r0 + 8) * N + c0) = make_float2(d[2], d[3]);
        }
    }
}

// ---------------------------------------------------------------------------
// Flash-attention (SIMT, unchanged): one block per (q-tile 64, head, batch).
// ---------------------------------------------------------------------------
#define ATTN_SMEM_FLOATS (2 * 64 * 65 + 64 * 65 + 64 * 64)
#define ATTN_SMEM_BYTES  (ATTN_SMEM_FLOATS * 4)

__global__ __launch_bounds__(64)
void attn_kernel()
{
    extern __shared__ float sm[];
    float* qs = sm;                 // [64][65]
    float* ks = qs + 64 * 65;       // [64][65]
    float* ss = ks + 64 * 65;       // [64][65]
    float* vs = ss + 64 * 65;       // [64][64]

    const int b  = blockIdx.z;
    const int h  = blockIdx.y;
    const int q0 = blockIdx.x * 64;
    const int r  = threadIdx.x;

    const float scale = 0.125f;

    for (int i = 0; i < 64; i++)
        qs[i * 65 + r] = g_qkv[((size_t)(b * SEQ + q0 + i)) * QKVN + h * HD + r];
    __syncthreads();

    float qreg[64];
#pragma unroll
    for (int d = 0; d < 64; d++) qreg[d] = qs[r * 65 + d];

    float acc[64];
#pragma unroll
    for (int d = 0; d < 64; d++) acc[d] = 0.f;
    float mval = -1e30f;
    float lval = 0.f;

    for (int kt = 0; kt < SEQ; kt += 64) {
        __syncthreads();
        for (int i = 0; i < 64; i++) {
            size_t base = ((size_t)(b * SEQ + kt + i)) * QKVN;
            ks[i * 65 + r] = g_qkv[base + DM     + h * HD + r];
            vs[i * 64 + r] = g_qkv[base + 2 * DM + h * HD + r];
        }
        __syncthreads();

        float rmax = mval;
        for (int j = 0; j < 64; j++) {
            float s0 = 0.f, s1 = 0.f, s2 = 0.f, s3 = 0.f;
#pragma unroll
            for (int d = 0; d < 64; d += 4) {
                s0 += qreg[d + 0] * ks[j * 65 + d + 0];
                s1 += qreg[d + 1] * ks[j * 65 + d + 1];
                s2 += qreg[d + 2] * ks[j * 65 + d + 2];
                s3 += qreg[d + 3] * ks[j * 65 + d + 3];
            }
            float s = ((s0 + s1) + (s2 + s3)) * scale;
            ss[r * 65 + j] = s;
            rmax = fmaxf(rmax, s);
        }

        const float corr = __expf(mval - rmax);
        mval = rmax;

        float lsum = 0.f;
        for (int j = 0; j < 64; j++) {
            float p = __expf(ss[r * 65 + j] - mval);
            ss[r * 65 + j] = p;
            lsum += p;
        }
        lval = lval * corr + lsum;

#pragma unroll
        for (int d = 0; d < 64; d++) acc[d] *= corr;

        for (int j = 0; j < 64; j++) {
            const float p = ss[r * 65 + j];
#pragma unroll
            for (int d = 0; d < 64; d++)
                acc[d] += p * vs[j * 64 + d];
        }
    }

    const float inv = 1.f / lval;
    float* outp = g_attn + ((size_t)(b * SEQ + q0 + r)) * DM + h * HD;
#pragma unroll
    for (int d = 0; d < 64; d++) outp[d] = acc[d] * inv;
}

// ---------------------------------------------------------------------------
extern "C" void kernel_launch(void* const* d_in, const int* in_sizes, int n_in,
                              void* d_out, int out_size)
{
    const float* x     = (const float*)d_in[0];   // [4,2048,1024]
    const float* w_qkv = (const float*)d_in[1];   // [1024,3072]
    const float* w_out = (const float*)d_in[2];   // [1024,1024]
    float* out = (float*)d_out;                   // [4,2048,1024]

    float* qkv_ptr;
    float* attn_ptr;
    cudaGetSymbolAddress((void**)&qkv_ptr,  g_qkv);
    cudaGetSymbolAddress((void**)&attn_ptr, g_attn);

    cudaFuncSetAttribute(gemm_hmma3,
                         cudaFuncAttributeMaxDynamicSharedMemorySize,
                         GEMM_SMEM_BYTES);
    cudaFuncSetAttribute(attn_kernel,
                         cudaFuncAttributeMaxDynamicSharedMemorySize,
                         ATTN_SMEM_BYTES);

    const int M = BATCH * SEQ;  // 8192

    // 1) QKV projection: [8192,1024] @ [1024,3072]
    {
        dim3 grid(QKVN / 128, M / 128);
        gemm_hmma3<<<grid, 256, GEMM_SMEM_BYTES>>>(x, w_qkv, qkv_ptr, M, QKVN, DM);
    }

    // 2) Attention
    {
        dim3 grid(SEQ / 64, NH, BATCH);
        attn_kernel<<<grid, 64, ATTN_SMEM_BYTES>>>();
    }

    // 3) Output projection: [8192,1024] @ [1024,1024]
    {
        dim3 grid(DM / 128, M / 128);
        gemm_hmma3<<<grid, 256, GEMM_SMEM_BYTES>>>(attn_ptr, w_out, out, M, DM, DM);
    }
}

// round 4
// speedup vs baseline: 3.9246x; 3.1888x over previous
#include <cuda_runtime.h>
#include <cuda_bf16.h>
#include <math.h>
#include <cstdint>

#define BATCH 4
#define SEQ   2048
#define DM    1024
#define NH    16
#define HD    64
#define QKVN  (3*DM)

// Scratch buffers (no dynamic allocation allowed)
__device__ float g_qkv[(size_t)BATCH * SEQ * QKVN];   // [B,S,3D]
__device__ float g_attn[(size_t)BATCH * SEQ * DM];    // [B,S,D]

// ===========================================================================
// Warp-level MMA helpers (base ISA: works on plain sm_103 target)
// ===========================================================================
__device__ __forceinline__ void ldsm_x4(uint32_t* r, uint32_t addr) {
    asm volatile("ldmatrix.sync.aligned.m8n8.x4.shared.b16 {%0,%1,%2,%3}, [%4];"
        : "=r"(r[0]), "=r"(r[1]), "=r"(r[2]), "=r"(r[3]) : "r"(addr));
}
__device__ __forceinline__ void ldsm_x4_t(uint32_t* r, uint32_t addr) {
    asm volatile("ldmatrix.sync.aligned.m8n8.x4.trans.shared.b16 {%0,%1,%2,%3}, [%4];"
        : "=r"(r[0]), "=r"(r[1]), "=r"(r[2]), "=r"(r[3]) : "r"(addr));
}
__device__ __forceinline__ void mma16816(float* d, const uint32_t* a, const uint32_t* b) {
    asm volatile(
        "mma.sync.aligned.m16n8k16.row.col.f32.bf16.bf16.f32 "
        "{%0,%1,%2,%3}, {%4,%5,%6,%7}, {%8,%9}, {%0,%1,%2,%3};"
        : "+f"(d[0]), "+f"(d[1]), "+f"(d[2]), "+f"(d[3])
        : "r"(a[0]), "r"(a[1]), "r"(a[2]), "r"(a[3]), "r"(b[0]), "r"(b[1]));
}

__device__ __forceinline__ uint32_t smem_to_u32(const void* smem_ptr) {
    uint32_t addr;
    asm("{ .reg .u64 tmp; cvta.to.shared.u64 tmp, %1; cvt.u32.u64 %0, tmp; }"
        : "=r"(addr) : "l"(smem_ptr));
    return addr;
}

__device__ __forceinline__ uint32_t pack_bf16_pair(float x0, float x1) {
    __nv_bfloat162 t = __floats2bfloat162_rn(x0, x1);
    return *(uint32_t*)&t;
}
__device__ __forceinline__ void split_f32(float x, float& h, float& l) {
    __nv_bfloat16 hb = __float2bfloat16_rn(x);
    h = __bfloat162float(hb);
    l = x - h;
}

// ===========================================================================
// HMMA bf16x3 GEMM: C[M,N] = A[M,K] @ B[K,N], fp32 in/out.
// CTA tile 128x128, BK=32, 256 threads (8 warps, 32x64 warp tiles).
// ===========================================================================
#define SA 40    // As row stride (bf16 elems)
#define SB 136   // Bs row stride (bf16 elems)
#define ABUF_B (128 * SA * 2)
#define BBUF_B (32 * SB * 2)
#define BUF_B  (2 * ABUF_B + 2 * BBUF_B)
#define GEMM_SMEM_BYTES (2 * BUF_B)      // 75776

__global__ __launch_bounds__(256, 1)
void gemm_hmma3(const float* __restrict__ A, const float* __restrict__ B,
                float* __restrict__ C, int M, int N, int K)
{
    extern __shared__ char smem[];
    const uint32_t smem_u32 = smem_to_u32(smem);

    const int tid = threadIdx.x;
    const int wid = tid >> 5;
    const int lid = tid & 31;
    const int brow = blockIdx.y * 128;
    const int bcol = blockIdx.x * 128;

    const int wr = wid >> 1;
    const int wc = wid & 1;

    float acc[2][8][4];
#pragma unroll
    for (int i = 0; i < 2; i++)
#pragma unroll
        for (int j = 0; j < 8; j++)
#pragma unroll
            for (int q = 0; q < 4; q++) acc[i][j][q] = 0.f;

    float4 pa[4], pb[4];
    const int nkt = K >> 5;

#pragma unroll
    for (int j = 0; j < 4; j++) {
        int idx = tid * 4 + j;
        pa[j] = *(const float4*)(A + (size_t)(brow + (idx >> 3)) * K + (idx & 7) * 4);
        pb[j] = *(const float4*)(B + (size_t)(idx >> 5) * N + bcol + (idx & 31) * 4);
    }

    for (int kt = 0; kt < nkt; kt++) {
        const int sW = kt & 1;
        {
            char* base = smem + sW * BUF_B;
#pragma unroll
            for (int j = 0; j < 4; j++) {
                int idx = tid * 4 + j;
                {
                    int r = idx >> 3, c = (idx & 7) * 4;
                    float h0,l0,h1,l1,h2,l2,h3,l3;
                    split_f32(pa[j].x, h0, l0); split_f32(pa[j].y, h1, l1);
                    split_f32(pa[j].z, h2, l2); split_f32(pa[j].w, h3, l3);
                    uint32_t off = (uint32_t)(r * SA + c) * 2;
                    *(uint2*)(base + off) =
                        make_uint2(pack_bf16_pair(h0, h1), pack_bf16_pair(h2, h3));
                    *(uint2*)(base + ABUF_B + off) =
                        make_uint2(pack_bf16_pair(l0, l1), pack_bf16_pair(l2, l3));
                }
                {
                    int r = idx >> 5, c = (idx & 31) * 4;
                    float h0,l0,h1,l1,h2,l2,h3,l3;
                    split_f32(pb[j].x, h0, l0); split_f32(pb[j].y, h1, l1);
                    split_f32(pb[j].z, h2, l2); split_f32(pb[j].w, h3, l3);
                    uint32_t off = (uint32_t)(r * SB + c) * 2;
                    *(uint2*)(base + 2 * ABUF_B + off) =
                        make_uint2(pack_bf16_pair(h0, h1), pack_bf16_pair(h2, h3));
                    *(uint2*)(base + 2 * ABUF_B + BBUF_B + off) =
                        make_uint2(pack_bf16_pair(l0, l1), pack_bf16_pair(l2, l3));
                }
            }
        }
        __syncthreads();

        if (kt + 1 < nkt) {
            const int k0 = (kt + 1) << 5;
#pragma unroll
            for (int j = 0; j < 4; j++) {
                int idx = tid * 4 + j;
                pa[j] = *(const float4*)(A + (size_t)(brow + (idx >> 3)) * K + k0 + (idx & 7) * 4);
                pb[j] = *(const float4*)(B + (size_t)(k0 + (idx >> 5)) * N + bcol + (idx & 31) * 4);
            }
        }

        const uint32_t aHi = smem_u32 + sW * BUF_B;
        const uint32_t aLo = aHi + ABUF_B;
        const uint32_t bHi = aHi + 2 * ABUF_B;
        const uint32_t bLo = bHi + BBUF_B;
#pragma unroll
        for (int ks = 0; ks < 2; ks++) {
            uint32_t ahi[2][4], alo[2][4];
#pragma unroll
            for (int mi = 0; mi < 2; mi++) {
                uint32_t row = wr * 32 + mi * 16 + (lid & 15);
                uint32_t col = ks * 16 + (lid >> 4) * 8;
                uint32_t off = (row * SA + col) * 2;
                ldsm_x4(ahi[mi], aHi + off);
                ldsm_x4(alo[mi], aLo + off);
            }
            uint32_t bhi[4][4], blo[4][4];
#pragma unroll
            for (int nb = 0; nb < 4; nb++) {
                uint32_t row = ks * 16 + (lid & 15);
                uint32_t col = wc * 64 + nb * 16 + (lid >> 4) * 8;
                uint32_t off = (row * SB + col) * 2;
                ldsm_x4_t(bhi[nb], bHi + off);
                ldsm_x4_t(blo[nb], bLo + off);
            }
#pragma unroll
            for (int mi = 0; mi < 2; mi++)
#pragma unroll
                for (int nb = 0; nb < 4; nb++) {
                    float* d0 = acc[mi][nb * 2];
                    float* d1 = acc[mi][nb * 2 + 1];
                    mma16816(d0, ahi[mi], &bhi[nb][0]);
                    mma16816(d1, ahi[mi], &bhi[nb][2]);
                    mma16816(d0, ahi[mi], &blo[nb][0]);
                    mma16816(d1, ahi[mi], &blo[nb][2]);
                    mma16816(d0, alo[mi], &bhi[nb][0]);
                    mma16816(d1, alo[mi], &bhi[nb][2]);
                }
        }
        __syncthreads();
    }

    const int qrow = lid >> 2;
    const int qcol = (lid & 3) * 2;
#pragma unroll
    for (int mi = 0; mi < 2; mi++) {
        int r0 = brow + wr * 32 + mi * 16 + qrow;
#pragma unroll
        for (int nb = 0; nb < 8; nb++) {
            int c0 = bcol + wc * 64 + nb * 8 + qcol;
            float* d = acc[mi][nb];
            *(float2*)(C + (size_t)r0 * N + c0)       = make_float2(d[0], d[1]);
            *(float2*)(C + (size_t)(r0 + 8) * N + c0) = make_float2(d[2], d[3]);
        }
    }
}

// ===========================================================================
// HMMA flash attention, bf16x3 for both QK^T and PV.
// Grid: (SEQ/128, NH, BATCH). 256 threads = 8 warps; warp w owns q rows
// [w*16, w*16+16) of a 128-row q tile. KV processed in blocks of 64.
// ===========================================================================
#define SK 72   // smem row stride in bf16 (144 B, 16B-aligned, conflict-free)

__global__ __launch_bounds__(256, 1)
void attn_hmma()
{
    __shared__ __align__(16) __nv_bfloat16 sKhi[64 * SK];
    __shared__ __align__(16) __nv_bfloat16 sKlo[64 * SK];
    __shared__ __align__(16) __nv_bfloat16 sVhi[64 * SK];
    __shared__ __align__(16) __nv_bfloat16 sVlo[64 * SK];

    const int tid = threadIdx.x;
    const int wid = tid >> 5;
    const int lid = tid & 31;
    const int b  = blockIdx.z;
    const int h  = blockIdx.y;
    const int q0 = blockIdx.x * 128;

    const uint32_t uKhi = smem_to_u32(sKhi);
    const uint32_t uKlo = smem_to_u32(sKlo);
    const uint32_t uVhi = smem_to_u32(sVhi);
    const uint32_t uVlo = smem_to_u32(sVlo);

    // ---- stage Q (scaled by 1/8) split hi/lo: rows 0-63 -> K bufs, 64-127 -> V bufs
    {
        const int r = tid >> 1;
        const int cofs = (tid & 1) * 32;
        const float* qp = g_qkv + ((size_t)(b * SEQ + q0 + r)) * QKVN + h * HD + cofs;
        __nv_bfloat16* dh = (r < 64 ? sKhi : sVhi) + (r & 63) * SK + cofs;
        __nv_bfloat16* dl = (r < 64 ? sKlo : sVlo) + (r & 63) * SK + cofs;
#pragma unroll
        for (int i = 0; i < 8; i++) {
            float4 v = *(const float4*)(qp + i * 4);
            float h0,l0,h1,l1,h2,l2,h3,l3;
            split_f32(v.x * 0.125f, h0, l0); split_f32(v.y * 0.125f, h1, l1);
            split_f32(v.z * 0.125f, h2, l2); split_f32(v.w * 0.125f, h3, l3);
            *(uint2*)((char*)dh + i * 8) =
                make_uint2(pack_bf16_pair(h0, h1), pack_bf16_pair(h2, h3));
            *(uint2*)((char*)dl + i * 8) =
                make_uint2(pack_bf16_pair(l0, l1), pack_bf16_pair(l2, l3));
        }
    }
    __syncthreads();

    // ---- load Q fragments to registers (A-operand layout)
    uint32_t qhi[4][4], qlo[4][4];
    {
        const uint32_t bh = (wid < 4) ? uKhi : uVhi;
        const uint32_t bl = (wid < 4) ? uKlo : uVlo;
        const uint32_t row = (wid & 3) * 16 + (lid & 15);
#pragma unroll
        for (int t = 0; t < 4; t++) {
            uint32_t off = (row * SK + t * 16 + (lid >> 4) * 8) * 2;
            ldsm_x4(qhi[t], bh + off);
            ldsm_x4(qlo[t], bl + off);
        }
    }
    __syncthreads();

    float o[8][4];
#pragma unroll
    for (int j = 0; j < 8; j++)
#pragma unroll
        for (int q = 0; q < 4; q++) o[j][q] = 0.f;
    float m0 = -1e30f, m1 = -1e30f, l0 = 0.f, l1 = 0.f;

    // ---- prefetch K/V block 0
    const int kr = tid >> 2;
    const int kc = (tid & 3) * 16;
    float4 pk[4], pv[4];
    {
        const float* kp = g_qkv + ((size_t)(b * SEQ + kr)) * QKVN + DM + h * HD + kc;
#pragma unroll
        for (int i = 0; i < 4; i++) {
            pk[i] = *(const float4*)(kp + i * 4);
            pv[i] = *(const float4*)(kp + DM + i * 4);
        }
    }

    for (int kb = 0; kb < SEQ / 64; kb++) {
        // ---- convert + store K/V block into smem
        {
            uint32_t off0 = (uint32_t)(kr * SK + kc) * 2;
#pragma unroll
            for (int i = 0; i < 4; i++) {
                float h0,l0_,h1,l1_,h2,l2_,h3,l3_;
                split_f32(pk[i].x, h0, l0_); split_f32(pk[i].y, h1, l1_);
                split_f32(pk[i].z, h2, l2_); split_f32(pk[i].w, h3, l3_);
                *(uint2*)((char*)sKhi + off0 + i * 8) =
                    make_uint2(pack_bf16_pair(h0, h1), pack_bf16_pair(h2, h3));
                *(uint2*)((char*)sKlo + off0 + i * 8) =
                    make_uint2(pack_bf16_pair(l0_, l1_), pack_bf16_pair(l2_, l3_));
                split_f32(pv[i].x, h0, l0_); split_f32(pv[i].y, h1, l1_);
                split_f32(pv[i].z, h2, l2_); split_f32(pv[i].w, h3, l3_);
                *(uint2*)((char*)sVhi + off0 + i * 8) =
                    make_uint2(pack_bf16_pair(h0, h1), pack_bf16_pair(h2, h3));
                *(uint2*)((char*)sVlo + off0 + i * 8) =
                    make_uint2(pack_bf16_pair(l0_, l1_), pack_bf16_pair(l2_, l3_));
            }
        }
        __syncthreads();

        // ---- prefetch next block
        if (kb + 1 < SEQ / 64) {
            const float* kp = g_qkv +
                ((size_t)(b * SEQ + (kb + 1) * 64 + kr)) * QKVN + DM + h * HD + kc;
#pragma unroll
            for (int i = 0; i < 4; i++) {
                pk[i] = *(const float4*)(kp + i * 4);
                pv[i] = *(const float4*)(kp + DM + i * 4);
            }
        }

        // ---- S = Q K^T  (16 x 64 per warp), bf16x3
        float s[8][4];
#pragma unroll
        for (int j = 0; j < 8; j++)
#pragma unroll
            for (int q = 0; q < 4; q++) s[j][q] = 0.f;

#pragma unroll
        for (int t = 0; t < 4; t++) {
#pragma unroll
            for (int j2 = 0; j2 < 4; j2++) {
                uint32_t kh[4], kl[4];
                uint32_t off = ((j2 * 16 + (lid & 7) + ((lid >> 4) & 1) * 8) * SK
                                + t * 16 + ((lid >> 3) & 1) * 8) * 2;
                ldsm_x4(kh, uKhi + off);
                ldsm_x4(kl, uKlo + off);
                float* d0 = s[j2 * 2];
                float* d1 = s[j2 * 2 + 1];
                mma16816(d0, qhi[t], &kh[0]); mma16816(d1, qhi[t], &kh[2]);
                mma16816(d0, qhi[t], &kl[0]); mma16816(d1, qhi[t], &kl[2]);
                mma16816(d0, qlo[t], &kh[0]); mma16816(d1, qlo[t], &kh[2]);
            }
        }

        // ---- online softmax
        float mx0 = s[0][0], mx1 = s[0][2];
#pragma unroll
        for (int j = 0; j < 8; j++) {
            mx0 = fmaxf(mx0, fmaxf(s[j][0], s[j][1]));
            mx1 = fmaxf(mx1, fmaxf(s[j][2], s[j][3]));
        }
        mx0 = fmaxf(mx0, __shfl_xor_sync(0xffffffff, mx0, 1));
        mx0 = fmaxf(mx0, __shfl_xor_sync(0xffffffff, mx0, 2));
        mx1 = fmaxf(mx1, __shfl_xor_sync(0xffffffff, mx1, 1));
        mx1 = fmaxf(mx1, __shfl_xor_sync(0xffffffff, mx1, 2));

        const float mn0 = fmaxf(m0, mx0);
        const float mn1 = fmaxf(m1, mx1);
        const float c0 = __expf(m0 - mn0);
        const float c1 = __expf(m1 - mn1);
        m0 = mn0; m1 = mn1;

        float rl0 = 0.f, rl1 = 0.f;
#pragma unroll
        for (int j = 0; j < 8; j++) {
            s[j][0] = __expf(s[j][0] - mn0); rl0 += s[j][0];
            s[j][1] = __expf(s[j][1] - mn0); rl0 += s[j][1];
            s[j][2] = __expf(s[j][2] - mn1); rl1 += s[j][2];
            s[j][3] = __expf(s[j][3] - mn1); rl1 += s[j][3];
        }
        rl0 += __shfl_xor_sync(0xffffffff, rl0, 1);
        rl0 += __shfl_xor_sync(0xffffffff, rl0, 2);
        rl1 += __shfl_xor_sync(0xffffffff, rl1, 1);
        rl1 += __shfl_xor_sync(0xffffffff, rl1, 2);
        l0 = l0 * c0 + rl0;
        l1 = l1 * c1 + rl1;

#pragma unroll
        for (int j = 0; j < 8; j++) {
            o[j][0] *= c0; o[j][1] *= c0;
            o[j][2] *= c1; o[j][3] *= c1;
        }

        // ---- pack P into A-fragments (hi/lo)
        uint32_t phi[4][4], plo[4][4];
#pragma unroll
        for (int t = 0; t < 4; t++) {
            const int j = 2 * t;
            float h0,lo0,h1,lo1;
            split_f32(s[j][0], h0, lo0);   split_f32(s[j][1], h1, lo1);
            phi[t][0] = pack_bf16_pair(h0, h1);  plo[t][0] = pack_bf16_pair(lo0, lo1);
            split_f32(s[j][2], h0, lo0);   split_f32(s[j][3], h1, lo1);
            phi[t][1] = pack_bf16_pair(h0, h1);  plo[t][1] = pack_bf16_pair(lo0, lo1);
            split_f32(s[j+1][0], h0, lo0); split_f32(s[j+1][1], h1, lo1);
            phi[t][2] = pack_bf16_pair(h0, h1);  plo[t][2] = pack_bf16_pair(lo0, lo1);
            split_f32(s[j+1][2], h0, lo0); split_f32(s[j+1][3], h1, lo1);
            phi[t][3] = pack_bf16_pair(h0, h1);  plo[t][3] = pack_bf16_pair(lo0, lo1);
        }

        // ---- O += P V  (bf16x3)
#pragma unroll
        for (int t = 0; t < 4; t++) {
#pragma unroll
            for (int j2 = 0; j2 < 4; j2++) {
                uint32_t vh[4], vl[4];
                uint32_t off = ((t * 16 + (lid & 15)) * SK
                                + j2 * 16 + (lid >> 4) * 8) * 2;
                ldsm_x4_t(vh, uVhi + off);
                ldsm_x4_t(vl, uVlo + off);
                float* d0 = o[j2 * 2];
                float* d1 = o[j2 * 2 + 1];
                mma16816(d0, phi[t], &vh[0]); mma16816(d1, phi[t], &vh[2]);
                mma16816(d0, phi[t], &vl[0]); mma16816(d1, phi[t], &vl[2]);
                mma16816(d0, plo[t], &vh[0]); mma16816(d1, plo[t], &vh[2]);
            }
        }
        __syncthreads();
    }

    // ---- epilogue
    const float inv0 = 1.f / l0;
    const float inv1 = 1.f / l1;
    const int gr0 = q0 + wid * 16 + (lid >> 2);
    const int col = h * HD + (lid & 3) * 2;
#pragma unroll
    for (int j = 0; j < 8; j++) {
        float* p0 = g_attn + ((size_t)(b * SEQ + gr0)) * DM + col + j * 8;
        float* p1 = g_attn + ((size_t)(b * SEQ + gr0 + 8)) * DM + col + j * 8;
        *(float2*)p0 = make_float2(o[j][0] * inv0, o[j][1] * inv0);
        *(float2*)p1 = make_float2(o[j][2] * inv1, o[j][3] * inv1);
    }
}

// ---------------------------------------------------------------------------
extern "C" void kernel_launch(void* const* d_in, const int* in_sizes, int n_in,
                              void* d_out, int out_size)
{
    const float* x     = (const float*)d_in[0];   // [4,2048,1024]
    const float* w_qkv = (const float*)d_in[1];   // [1024,3072]
    const float* w_out = (const float*)d_in[2];   // [1024,1024]
    float* out = (float*)d_out;                   // [4,2048,1024]

    float* qkv_ptr;
    float* attn_ptr;
    cudaGetSymbolAddress((void**)&qkv_ptr,  g_qkv);
    cudaGetSymbolAddress((void**)&attn_ptr, g_attn);

    cudaFuncSetAttribute(gemm_hmma3,
                         cudaFuncAttributeMaxDynamicSharedMemorySize,
                         GEMM_SMEM_BYTES);

    const int M = BATCH * SEQ;  // 8192

    // 1) QKV projection: [8192,1024] @ [1024,3072]
    {
        dim3 grid(QKVN / 128, M / 128);
        gemm_hmma3<<<grid, 256, GEMM_SMEM_BYTES>>>(x, w_qkv, qkv_ptr, M, QKVN, DM);
    }

    // 2) Attention (HMMA flash)
    {
        dim3 grid(SEQ / 128, NH, BATCH);
        attn_hmma<<<grid, 256>>>();
    }

    // 3) Output projection: [8192,1024] @ [1024,1024]
    {
        dim3 grid(DM / 128, M / 128);
        gemm_hmma3<<<grid, 256, GEMM_SMEM_BYTES>>>(attn_ptr, w_out, out, M, DM, DM);
    }
}